// round 13
// baseline (speedup 1.0000x reference)
#include <cuda_runtime.h>
#include <cuda_bf16.h>
#include <cuda_fp16.h>

#define Nn 100000
#define Ee 1600000
#define Dd 32
#define MAXD 64                      // slots per node (max real degree ~35)

// Packed f32x2 helpers (sm_100a FFMA2 — only reachable via PTX)
#define PACK2(out, f) \
    asm("mov.b64 %0, {%1, %1};" : "=l"(out) : "r"(__float_as_uint(f)))
#define FMA2(acc, a, b) \
    asm("fma.rn.f32x2 %0, %1, %2, %0;" : "+l"(acc) : "l"(a), "l"(b))
#define UNPACK2(lo, hi, in) \
    asm("mov.b64 {%0, %1}, %2;" : "=r"(lo), "=r"(hi) : "l"(in))

// Fast ELU: for v<0, exp(v)-1 via MUFU (expm1f is a libdevice slow path)
__device__ __forceinline__ float fast_elu(float v) {
    return v > 0.f ? v : __expf(v) - 1.f;
}

__device__ __forceinline__ float leaky02(float a) {
    return a > 0.f ? a : 0.2f * a;
}

// ---------------- device scratch (no allocations allowed) ----------------
__device__ __align__(16) float g_h[Nn * Dd];   // h = in @ W (fp32 rows, 128B)
__device__ float g_as[Nn];           // alpha_src per node
__device__ float g_ad[Nn];           // alpha_dst per node
__device__ int   g_cur[Nn];          // per-node fill cursor == edge in-degree
                                     // (zero-init; re-armed by layer-2 k_node)
__device__ int   g_sorted[Nn * MAXD]; // src indices, fixed-stride slab per dst

// ---------------------------------------------------------------------------
// Bucket scatter: fixed-stride slab per destination, no histogram/offsets.
// 4 edges per thread (int4): 4 independent atomic chains in flight.
// g_cur is zero on entry: zeroed at static init for the first call, and
// reset by the layer-2 k_node at the end of every call thereafter.
// ---------------------------------------------------------------------------
__global__ void k_scatter(const int4* __restrict__ src4,
                          const int4* __restrict__ dst4) {
    int i = blockIdx.x * blockDim.x + threadIdx.x;
    if (i >= Ee / 4) return;
    int4 s = src4[i];
    int4 d = dst4[i];
    int p0 = atomicAdd(&g_cur[d.x], 1);
    int p1 = atomicAdd(&g_cur[d.y], 1);
    int p2 = atomicAdd(&g_cur[d.z], 1);
    int p3 = atomicAdd(&g_cur[d.w], 1);
    g_sorted[(d.x << 6) + p0] = s.x;
    g_sorted[(d.y << 6) + p1] = s.y;
    g_sorted[(d.z << 6) + p2] = s.z;
    g_sorted[(d.w << 6) + p3] = s.w;
}

// ---------------------------------------------------------------------------
// GEMM + alpha: h = in @ W (N x 32 @ 32 x 32), per-node dot products with
// a_src / a_dst. One warp per row. fp32 throughout.
// ---------------------------------------------------------------------------
__global__ void k_gemm_alpha(const float* __restrict__ in,
                             const float* __restrict__ W,
                             const float* __restrict__ a_s,
                             const float* __restrict__ a_d) {
    __shared__ float Ws[Dd * Dd];
    __shared__ float asv[Dd];
    __shared__ float adv[Dd];
    int tid = threadIdx.x;
    for (int i = tid; i < Dd * Dd; i += blockDim.x) Ws[i] = W[i];
    if (tid < Dd) { asv[tid] = a_s[tid]; adv[tid] = a_d[tid]; }
    __syncthreads();

    int warp = tid >> 5;
    int lane = tid & 31;
    int row = blockIdx.x * (blockDim.x >> 5) + warp;
    if (row >= Nn) return;

    float xr = in[row * Dd + lane];
    float h = 0.f;
#pragma unroll
    for (int k = 0; k < Dd; k++)
        h = fmaf(__shfl_sync(0xffffffffu, xr, k), Ws[k * Dd + lane], h);

    g_h[row * Dd + lane] = h;

    float vs = h * asv[lane];
    float vd = h * adv[lane];
#pragma unroll
    for (int o = 16; o > 0; o >>= 1) {
        vs += __shfl_xor_sync(0xffffffffu, vs, o);
        vd += __shfl_xor_sync(0xffffffffu, vd, o);
    }
    if (lane == 0) {
        g_as[row] = vs;
        g_ad[row] = vd;
    }
}

// ---------------------------------------------------------------------------
// Fused per-node GAT aggregation: TWO nodes per warp (16 lanes each).
// Single-shot 32-edge prologue per node: both 16-edge sub-batches loaded
// upfront as independent chains. deg > 32 handled by a rare uniform tail.
// reset != 0 (layer 2): re-arm g_cur[node] = 0 for the next graph replay.
// Softmax max-subtraction omitted (shift-invariant; alpha is O(10) bounded).
// ---------------------------------------------------------------------------
__global__ void __launch_bounds__(256, 8) k_node(const float* __restrict__ bias,
                                                 float* __restrict__ out,
                                                 int reset) {
    int warpid = (blockIdx.x * blockDim.x + threadIdx.x) >> 5;
    int lane = threadIdx.x & 31;
    int n0 = warpid << 1;
    if (n0 >= Nn) return;                          // Nn even -> n0+1 valid
    int half = lane >> 4;
    int hl   = lane & 15;
    int node = n0 + half;
    int eq   = hl >> 3;                            // 0/1: edge within pair
    int cs   = (hl & 7) << 2;                      // column start (4 cols)

    int   deg = g_cur[node];
    float adv = g_ad[node];
    int  slab = node << 6;

    // ---- prologue: 32 edge slots, two independent chains ----
    int s_lo = g_sorted[slab + hl];
    int s_hi = g_sorted[slab + 16 + hl];
    float as_lo = g_as[s_lo];                      // slots always readable
    float as_hi = g_as[s_hi];

    // self loop (independent chain too)
    float a0 = g_as[node] + adv;
    float w0 = __expf(leaky02(a0));
    const float4 hs = *(const float4*)(g_h + node * Dd + cs);

    if (reset && hl == 0) g_cur[node] = 0;         // re-arm for next replay

    float w_lo = (hl      < deg) ? __expf(leaky02(as_lo + adv)) : 0.f;
    float w_hi = (hl + 16 < deg) ? __expf(leaky02(as_hi + adv)) : 0.f;
    float wsum = w_lo + w_hi;

    int dmax = max(deg, __shfl_xor_sync(0xffffffffu, deg, 16));

    unsigned long long pacc0 = 0ull, pacc1 = 0ull; // packed float2 accums
    int sbase = (half << 4) + eq;                  // shfl source base

    // ---- FMA over lo edges (0..15) ----
#pragma unroll
    for (int j = 0; j < 16; j += 2) {
        if (j >= dmax) break;                      // uniform
        int   sj = __shfl_sync(0xffffffffu, s_lo, sbase + j);
        float wj = __shfl_sync(0xffffffffu, w_lo, sbase + j);
        ulonglong2 r = *(const ulonglong2*)(g_h + sj * Dd + cs);
        unsigned long long w2;
        PACK2(w2, wj);
        FMA2(pacc0, w2, r.x);
        FMA2(pacc1, w2, r.y);
    }
    // ---- FMA over hi edges (16..31) ----
#pragma unroll
    for (int j = 0; j < 16; j += 2) {
        if (j + 16 >= dmax) break;                 // uniform
        int   sj = __shfl_sync(0xffffffffu, s_hi, sbase + j);
        float wj = __shfl_sync(0xffffffffu, w_hi, sbase + j);
        ulonglong2 r = *(const ulonglong2*)(g_h + sj * Dd + cs);
        unsigned long long w2;
        PACK2(w2, wj);
        FMA2(pacc0, w2, r.x);
        FMA2(pacc1, w2, r.y);
    }

    // ---- rare tail: deg > 32 (uniform across warp) ----
    if (dmax > 32) {
        for (int k0 = 32; k0 < dmax; k0 += 16) {
            int idx = k0 + hl;
            int s = g_sorted[slab + (idx & 63)];
            float w = 0.f;
            if (idx < deg) w = __expf(leaky02(g_as[s] + adv));
            wsum += w;
            int nb = dmax - k0; if (nb > 16) nb = 16;
#pragma unroll
            for (int j = 0; j < 16; j += 2) {
                if (j >= nb) break;
                int   sj = __shfl_sync(0xffffffffu, s, sbase + j);
                float wj = __shfl_sync(0xffffffffu, w, sbase + j);
                ulonglong2 r = *(const ulonglong2*)(g_h + sj * Dd + cs);
                unsigned long long w2;
                PACK2(w2, wj);
                FMA2(pacc0, w2, r.x);
                FMA2(pacc1, w2, r.y);
            }
        }
    }

    unsigned int u0, u1, u2, u3;
    UNPACK2(u0, u1, pacc0);
    UNPACK2(u2, u3, pacc1);
    float acc0 = __uint_as_float(u0);
    float acc1 = __uint_as_float(u1);
    float acc2 = __uint_as_float(u2);
    float acc3 = __uint_as_float(u3);

    const float4 b4 = *(const float4*)(bias + cs); // hoisted: overlaps shfls

    // combine the 2 edge groups (offset 8, within each half)
    acc0 += __shfl_xor_sync(0xffffffffu, acc0, 8);
    acc1 += __shfl_xor_sync(0xffffffffu, acc1, 8);
    acc2 += __shfl_xor_sync(0xffffffffu, acc2, 8);
    acc3 += __shfl_xor_sync(0xffffffffu, acc3, 8);
    // wsum: reduce within the 16-lane half
#pragma unroll
    for (int o = 8; o > 0; o >>= 1)
        wsum += __shfl_xor_sync(0xffffffffu, wsum, o);

    // self loop contribution (once)
    acc0 = fmaf(w0, hs.x, acc0);
    acc1 = fmaf(w0, hs.y, acc1);
    acc2 = fmaf(w0, hs.z, acc2);
    acc3 = fmaf(w0, hs.w, acc3);
    wsum += w0;

    if (hl < 8) {                                  // 16 active lanes: 2 nodes
        float scale = __fdividef(1.f, wsum);
        float4 v;
        v.x = fmaf(acc0, scale, b4.x);
        v.y = fmaf(acc1, scale, b4.y);
        v.z = fmaf(acc2, scale, b4.z);
        v.w = fmaf(acc3, scale, b4.w);
        v.x = fast_elu(v.x);
        v.y = fast_elu(v.y);
        v.z = fast_elu(v.z);
        v.w = fast_elu(v.w);
        *(float4*)(out + node * Dd + cs) = v;
    }
}

// ---------------------------------------------------------------------------
extern "C" void kernel_launch(void* const* d_in, const int* in_sizes, int n_in,
                              void* d_out, int out_size) {
    const float* x    = (const float*)d_in[0];
    const int*   ei   = (const int*)d_in[1];
    const int4*  src4 = (const int4*)ei;
    const int4*  dst4 = (const int4*)(ei + Ee);
    const float* W1   = (const float*)d_in[2];
    const float* as1  = (const float*)d_in[3];
    const float* ad1  = (const float*)d_in[4];
    const float* b1   = (const float*)d_in[5];
    const float* W2   = (const float*)d_in[6];
    const float* as2  = (const float*)d_in[7];
    const float* ad2  = (const float*)d_in[8];
    const float* b2   = (const float*)d_in[9];

    float* xbar = (float*)d_out;            // first N*D: xbar
    float* z    = (float*)d_out + Nn * Dd;  // second N*D: z

    const int TPB = 256;
    const int E4  = Ee / 4;

    // ---- bucket build (shared by both layers); g_cur re-armed by layer 2 ----
    k_scatter<<<(E4 + TPB - 1) / TPB, TPB>>>(src4, dst4);

    const int gGemm = (Nn + 7) / 8;         // 8 warps/block, 1 row/warp
    const int gNode = (Nn / 2 + 7) / 8;     // 8 warps/block, 2 nodes/warp

    // ---- Layer 1 ----
    k_gemm_alpha<<<gGemm, TPB>>>(x, W1, as1, ad1);
    k_node      <<<gNode, TPB>>>(b1, z, 0);

    // ---- Layer 2 (resets g_cur for the next graph replay) ----
    k_gemm_alpha<<<gGemm, TPB>>>(z, W2, as2, ad2);
    k_node      <<<gNode, TPB>>>(b2, xbar, 1);
}

// round 14
// speedup vs baseline: 1.3112x; 1.3112x over previous
#include <cuda_runtime.h>
#include <cuda_bf16.h>
#include <cuda_fp16.h>

#define Nn 100000
#define Ee 1600000
#define Dd 32
#define MAXD 64                      // slots per node (max real degree ~35)

// Packed f32x2 helpers (sm_100a FFMA2 — only reachable via PTX)
#define PACK2(out, f) \
    asm("mov.b64 %0, {%1, %1};" : "=l"(out) : "r"(__float_as_uint(f)))
#define FMA2(acc, a, b) \
    asm("fma.rn.f32x2 %0, %1, %2, %0;" : "+l"(acc) : "l"(a), "l"(b))
#define UNPACK2(lo, hi, in) \
    asm("mov.b64 {%0, %1}, %2;" : "=r"(lo), "=r"(hi) : "l"(in))

// Fast ELU: for v<0, exp(v)-1 via MUFU (expm1f is a libdevice slow path)
__device__ __forceinline__ float fast_elu(float v) {
    return v > 0.f ? v : __expf(v) - 1.f;
}

__device__ __forceinline__ float leaky02(float a) {
    return a > 0.f ? a : 0.2f * a;
}

// ---------------- device scratch (no allocations allowed) ----------------
__device__ __align__(16) float g_h[Nn * Dd];   // h = in @ W (fp32 rows, 128B)
__device__ float g_as[Nn];           // alpha_src per node
__device__ float g_ad[Nn];           // alpha_dst per node
__device__ int   g_cur[Nn];          // per-node fill cursor == edge in-degree
                                     // (zero-init; re-armed by layer-2 k_node)
__device__ int   g_sorted[Nn * MAXD]; // src indices, fixed-stride slab per dst

// ---------------------------------------------------------------------------
// Bucket scatter: fixed-stride slab per destination, no histogram/offsets.
// 4 edges per thread (int4): 4 independent atomic chains in flight.
// g_cur is zero on entry: zeroed at static init for the first call, and
// reset by the layer-2 k_node at the end of every call thereafter.
// ---------------------------------------------------------------------------
__global__ void k_scatter(const int4* __restrict__ src4,
                          const int4* __restrict__ dst4) {
    int i = blockIdx.x * blockDim.x + threadIdx.x;
    if (i >= Ee / 4) return;
    int4 s = src4[i];
    int4 d = dst4[i];
    int p0 = atomicAdd(&g_cur[d.x], 1);
    int p1 = atomicAdd(&g_cur[d.y], 1);
    int p2 = atomicAdd(&g_cur[d.z], 1);
    int p3 = atomicAdd(&g_cur[d.w], 1);
    g_sorted[(d.x << 6) + p0] = s.x;
    g_sorted[(d.y << 6) + p1] = s.y;
    g_sorted[(d.z << 6) + p2] = s.z;
    g_sorted[(d.w << 6) + p3] = s.w;
}

// ---------------------------------------------------------------------------
// GEMM + alpha, THREAD-PER-ROW (no shuffles — the old warp-per-row form
// saturated the MIO pipe with 32 SHFL + 32 LDS per row).
// Each thread: 32 fp32 accumulators, x streamed as float4, W rows broadcast
// from smem (uniform LDS.128, conflict-free). Alpha dots are thread-local.
// ---------------------------------------------------------------------------
__global__ void __launch_bounds__(256) k_gemm_alpha(
        const float* __restrict__ in,
        const float* __restrict__ W,
        const float* __restrict__ a_s,
        const float* __restrict__ a_d) {
    __shared__ float Ws[Dd * Dd];
    __shared__ float av[2 * Dd];                   // [asv | adv]
    int tid = threadIdx.x;
    for (int i = tid; i < Dd * Dd; i += 256) Ws[i] = W[i];
    if (tid < Dd) { av[tid] = a_s[tid]; av[Dd + tid] = a_d[tid]; }
    __syncthreads();

    int row = blockIdx.x * 256 + tid;
    if (row >= Nn) return;

    const float4* xr = (const float4*)(in + row * Dd);
    float acc[Dd];
#pragma unroll
    for (int c = 0; c < Dd; c++) acc[c] = 0.f;

#pragma unroll 2
    for (int k4 = 0; k4 < Dd / 4; k4++) {
        float4 x4 = xr[k4];
#pragma unroll
        for (int kk = 0; kk < 4; kk++) {
            float xk = (kk == 0) ? x4.x : (kk == 1) ? x4.y
                     : (kk == 2) ? x4.z : x4.w;
            const float4* wrow = (const float4*)(Ws + (k4 * 4 + kk) * Dd);
#pragma unroll
            for (int c4 = 0; c4 < Dd / 4; c4++) {
                float4 w4 = wrow[c4];
                acc[c4 * 4 + 0] = fmaf(xk, w4.x, acc[c4 * 4 + 0]);
                acc[c4 * 4 + 1] = fmaf(xk, w4.y, acc[c4 * 4 + 1]);
                acc[c4 * 4 + 2] = fmaf(xk, w4.z, acc[c4 * 4 + 2]);
                acc[c4 * 4 + 3] = fmaf(xk, w4.w, acc[c4 * 4 + 3]);
            }
        }
    }

    // store h + thread-local alpha dot products (no reductions needed)
    float4* hout = (float4*)(g_h + row * Dd);
    float vs = 0.f, vd = 0.f;
#pragma unroll
    for (int c4 = 0; c4 < Dd / 4; c4++) {
        float4 o = make_float4(acc[c4 * 4 + 0], acc[c4 * 4 + 1],
                               acc[c4 * 4 + 2], acc[c4 * 4 + 3]);
        hout[c4] = o;
        const float4 s4 = *(const float4*)(av + c4 * 4);
        const float4 d4 = *(const float4*)(av + Dd + c4 * 4);
        vs = fmaf(o.x, s4.x, vs); vs = fmaf(o.y, s4.y, vs);
        vs = fmaf(o.z, s4.z, vs); vs = fmaf(o.w, s4.w, vs);
        vd = fmaf(o.x, d4.x, vd); vd = fmaf(o.y, d4.y, vd);
        vd = fmaf(o.z, d4.z, vd); vd = fmaf(o.w, d4.w, vd);
    }
    g_as[row] = vs;
    g_ad[row] = vd;
}

// ---------------------------------------------------------------------------
// Fused per-node GAT aggregation: TWO nodes per warp (16 lanes each).
// Single-shot 32-edge prologue per node; deg > 32 via rare uniform tail.
// reset != 0 (layer 2): re-arm g_cur[node] = 0 for the next graph replay.
// Softmax max-subtraction omitted (shift-invariant; alpha is O(10) bounded).
// ---------------------------------------------------------------------------
__global__ void __launch_bounds__(256, 8) k_node(const float* __restrict__ bias,
                                                 float* __restrict__ out,
                                                 int reset) {
    int warpid = (blockIdx.x * blockDim.x + threadIdx.x) >> 5;
    int lane = threadIdx.x & 31;
    int n0 = warpid << 1;
    if (n0 >= Nn) return;                          // Nn even -> n0+1 valid
    int half = lane >> 4;
    int hl   = lane & 15;
    int node = n0 + half;
    int eq   = hl >> 3;                            // 0/1: edge within pair
    int cs   = (hl & 7) << 2;                      // column start (4 cols)

    int   deg = g_cur[node];
    float adv = g_ad[node];
    int  slab = node << 6;

    // ---- prologue: 32 edge slots, two independent chains ----
    int s_lo = g_sorted[slab + hl];
    int s_hi = g_sorted[slab + 16 + hl];
    float as_lo = g_as[s_lo];                      // slots always readable
    float as_hi = g_as[s_hi];

    // self loop (independent chain too)
    float a0 = g_as[node] + adv;
    float w0 = __expf(leaky02(a0));
    const float4 hs = *(const float4*)(g_h + node * Dd + cs);

    if (reset && hl == 0) g_cur[node] = 0;         // re-arm for next replay

    float w_lo = (hl      < deg) ? __expf(leaky02(as_lo + adv)) : 0.f;
    float w_hi = (hl + 16 < deg) ? __expf(leaky02(as_hi + adv)) : 0.f;
    float wsum = w_lo + w_hi;

    int dmax = max(deg, __shfl_xor_sync(0xffffffffu, deg, 16));

    unsigned long long pacc0 = 0ull, pacc1 = 0ull; // packed float2 accums
    int sbase = (half << 4) + eq;                  // shfl source base

    // ---- FMA over lo edges (0..15) ----
#pragma unroll
    for (int j = 0; j < 16; j += 2) {
        if (j >= dmax) break;                      // uniform
        int   sj = __shfl_sync(0xffffffffu, s_lo, sbase + j);
        float wj = __shfl_sync(0xffffffffu, w_lo, sbase + j);
        ulonglong2 r = *(const ulonglong2*)(g_h + sj * Dd + cs);
        unsigned long long w2;
        PACK2(w2, wj);
        FMA2(pacc0, w2, r.x);
        FMA2(pacc1, w2, r.y);
    }
    // ---- FMA over hi edges (16..31) ----
#pragma unroll
    for (int j = 0; j < 16; j += 2) {
        if (j + 16 >= dmax) break;                 // uniform
        int   sj = __shfl_sync(0xffffffffu, s_hi, sbase + j);
        float wj = __shfl_sync(0xffffffffu, w_hi, sbase + j);
        ulonglong2 r = *(const ulonglong2*)(g_h + sj * Dd + cs);
        unsigned long long w2;
        PACK2(w2, wj);
        FMA2(pacc0, w2, r.x);
        FMA2(pacc1, w2, r.y);
    }

    // ---- rare tail: deg > 32 (uniform across warp) ----
    if (dmax > 32) {
        for (int k0 = 32; k0 < dmax; k0 += 16) {
            int idx = k0 + hl;
            int s = g_sorted[slab + (idx & 63)];
            float w = 0.f;
            if (idx < deg) w = __expf(leaky02(g_as[s] + adv));
            wsum += w;
            int nb = dmax - k0; if (nb > 16) nb = 16;
#pragma unroll
            for (int j = 0; j < 16; j += 2) {
                if (j >= nb) break;
                int   sj = __shfl_sync(0xffffffffu, s, sbase + j);
                float wj = __shfl_sync(0xffffffffu, w, sbase + j);
                ulonglong2 r = *(const ulonglong2*)(g_h + sj * Dd + cs);
                unsigned long long w2;
                PACK2(w2, wj);
                FMA2(pacc0, w2, r.x);
                FMA2(pacc1, w2, r.y);
            }
        }
    }

    unsigned int u0, u1, u2, u3;
    UNPACK2(u0, u1, pacc0);
    UNPACK2(u2, u3, pacc1);
    float acc0 = __uint_as_float(u0);
    float acc1 = __uint_as_float(u1);
    float acc2 = __uint_as_float(u2);
    float acc3 = __uint_as_float(u3);

    const float4 b4 = *(const float4*)(bias + cs); // hoisted: overlaps shfls

    // combine the 2 edge groups (offset 8, within each half)
    acc0 += __shfl_xor_sync(0xffffffffu, acc0, 8);
    acc1 += __shfl_xor_sync(0xffffffffu, acc1, 8);
    acc2 += __shfl_xor_sync(0xffffffffu, acc2, 8);
    acc3 += __shfl_xor_sync(0xffffffffu, acc3, 8);
    // wsum: reduce within the 16-lane half
#pragma unroll
    for (int o = 8; o > 0; o >>= 1)
        wsum += __shfl_xor_sync(0xffffffffu, wsum, o);

    // self loop contribution (once)
    acc0 = fmaf(w0, hs.x, acc0);
    acc1 = fmaf(w0, hs.y, acc1);
    acc2 = fmaf(w0, hs.z, acc2);
    acc3 = fmaf(w0, hs.w, acc3);
    wsum += w0;

    if (hl < 8) {                                  // 16 active lanes: 2 nodes
        float scale = __fdividef(1.f, wsum);
        float4 v;
        v.x = fmaf(acc0, scale, b4.x);
        v.y = fmaf(acc1, scale, b4.y);
        v.z = fmaf(acc2, scale, b4.z);
        v.w = fmaf(acc3, scale, b4.w);
        v.x = fast_elu(v.x);
        v.y = fast_elu(v.y);
        v.z = fast_elu(v.z);
        v.w = fast_elu(v.w);
        *(float4*)(out + node * Dd + cs) = v;
    }
}

// ---------------------------------------------------------------------------
extern "C" void kernel_launch(void* const* d_in, const int* in_sizes, int n_in,
                              void* d_out, int out_size) {
    const float* x    = (const float*)d_in[0];
    const int*   ei   = (const int*)d_in[1];
    const int4*  src4 = (const int4*)ei;
    const int4*  dst4 = (const int4*)(ei + Ee);
    const float* W1   = (const float*)d_in[2];
    const float* as1  = (const float*)d_in[3];
    const float* ad1  = (const float*)d_in[4];
    const float* b1   = (const float*)d_in[5];
    const float* W2   = (const float*)d_in[6];
    const float* as2  = (const float*)d_in[7];
    const float* ad2  = (const float*)d_in[8];
    const float* b2   = (const float*)d_in[9];

    float* xbar = (float*)d_out;            // first N*D: xbar
    float* z    = (float*)d_out + Nn * Dd;  // second N*D: z

    const int TPB = 256;
    const int E4  = Ee / 4;

    // ---- bucket build (shared by both layers); g_cur re-armed by layer 2 ----
    k_scatter<<<(E4 + TPB - 1) / TPB, TPB>>>(src4, dst4);

    const int gGemm = (Nn + 255) / 256;     // thread per row
    const int gNode = (Nn / 2 + 7) / 8;     // 8 warps/block, 2 nodes/warp

    // ---- Layer 1 ----
    k_gemm_alpha<<<gGemm, TPB>>>(x, W1, as1, ad1);
    k_node      <<<gNode, TPB>>>(b1, z, 0);

    // ---- Layer 2 (resets g_cur for the next graph replay) ----
    k_gemm_alpha<<<gGemm, TPB>>>(z, W2, as2, ad2);
    k_node      <<<gNode, TPB>>>(b2, xbar, 1);
}

// round 16
// speedup vs baseline: 1.4302x; 1.0907x over previous
#include <cuda_runtime.h>
#include <cuda_bf16.h>
#include <cuda_fp16.h>

#define Nn 100000
#define Ee 1600000
#define Dd 32
#define MAXD 64                      // slots per node (max real degree ~35)
#define XT_STRIDE 260                // 256 rows + pad, multiple of 4 for LDS.128

// Packed f32x2 helpers (sm_100a FFMA2 — only reachable via PTX)
#define PACK2(out, f) \
    asm("mov.b64 %0, {%1, %1};" : "=l"(out) : "r"(__float_as_uint(f)))
#define PACKAB(out, a, b) \
    asm("mov.b64 %0, {%1, %2};" : "=l"(out) : "f"(a), "f"(b))
#define FMA2(acc, a, b) \
    asm("fma.rn.f32x2 %0, %1, %2, %0;" : "+l"(acc) : "l"(a), "l"(b))
#define UNPACK2(lo, hi, in) \
    asm("mov.b64 {%0, %1}, %2;" : "=r"(lo), "=r"(hi) : "l"(in))

// Fast ELU: for v<0, exp(v)-1 via MUFU (expm1f is a libdevice slow path)
__device__ __forceinline__ float fast_elu(float v) {
    return v > 0.f ? v : __expf(v) - 1.f;
}

__device__ __forceinline__ float leaky02(float a) {
    return a > 0.f ? a : 0.2f * a;
}

// ---------------- device scratch (no allocations allowed) ----------------
__device__ __align__(16) float g_h[Nn * Dd];   // h = in @ W (fp32 rows, 128B)
__device__ float g_as[Nn];           // alpha_src per node
__device__ float g_ad[Nn];           // alpha_dst per node
__device__ int   g_cur[Nn];          // per-node fill cursor == edge in-degree
                                     // (zero-init; re-armed by layer-2 k_node)
__device__ int   g_sorted[Nn * MAXD]; // src indices, fixed-stride slab per dst

// ---------------------------------------------------------------------------
// Bucket scatter: fixed-stride slab per destination, no histogram/offsets.
// 4 edges per thread (int4): 4 independent atomic chains in flight.
// ---------------------------------------------------------------------------
__global__ void k_scatter(const int4* __restrict__ src4,
                          const int4* __restrict__ dst4) {
    int i = blockIdx.x * blockDim.x + threadIdx.x;
    if (i >= Ee / 4) return;
    int4 s = src4[i];
    int4 d = dst4[i];
    int p0 = atomicAdd(&g_cur[d.x], 1);
    int p1 = atomicAdd(&g_cur[d.y], 1);
    int p2 = atomicAdd(&g_cur[d.z], 1);
    int p3 = atomicAdd(&g_cur[d.w], 1);
    g_sorted[(d.x << 6) + p0] = s.x;
    g_sorted[(d.y << 6) + p1] = s.y;
    g_sorted[(d.z << 6) + p2] = s.z;
    g_sorted[(d.w << 6) + p3] = s.w;
}

// ---------------------------------------------------------------------------
// GEMM + alpha, register-blocked: each thread computes 8 rows x 8 cols.
// Block = 128 threads = 32 row-groups x 4 col-groups -> 256 rows/block.
// x staged transposed in smem (coalesced global loads); W smem fetches are
// reused across 8 rows (32x fewer LDS than thread-per-row). FFMA2 accums.
// ---------------------------------------------------------------------------
__global__ void __launch_bounds__(128) k_gemm_alpha(
        const float* __restrict__ in,
        const float* __restrict__ W,
        const float* __restrict__ a_s,
        const float* __restrict__ a_d) {
    __shared__ float Ws[Dd * Dd];
    __shared__ float av[2 * Dd];                   // [a_src | a_dst]
    __shared__ float xT[Dd * XT_STRIDE];           // transposed x tile

    int tid = threadIdx.x;
    for (int i = tid; i < Dd * Dd; i += 128) Ws[i] = W[i];
    if (tid < Dd) { av[tid] = a_s[tid]; av[Dd + tid] = a_d[tid]; }

    int rowbase = blockIdx.x * 256;
    int nrows = Nn - rowbase; if (nrows > 256) nrows = 256;

    // stage: 256 rows x 32 cols, coalesced float4 loads, transposed stores
    const float4* xg = (const float4*)(in + rowbase * Dd);
#pragma unroll
    for (int i = 0; i < 16; i++) {
        int f = tid + i * 128;
        int row = f >> 3;
        if (f < 2048 && row < nrows) {
            float4 v = xg[f];
            int k = (f & 7) << 2;
            xT[(k + 0) * XT_STRIDE + row] = v.x;
            xT[(k + 1) * XT_STRIDE + row] = v.y;
            xT[(k + 2) * XT_STRIDE + row] = v.z;
            xT[(k + 3) * XT_STRIDE + row] = v.w;
        }
    }
    __syncthreads();

    int cg = tid & 3;                              // col group: cols 8cg..8cg+7
    int rg = tid >> 2;                             // row group: rows 8rg..8rg+7
    int r0 = rg << 3;
    if (r0 >= nrows) return;                       // after the only sync
                                                   // (quad-uniform: all 4
                                                   //  lanes share rg)

    unsigned long long acc[8][4];
#pragma unroll
    for (int r = 0; r < 8; r++)
#pragma unroll
        for (int p = 0; p < 4; p++) acc[r][p] = 0ull;

    const float* wbase = Ws + cg * 8;
#pragma unroll 4
    for (int k = 0; k < Dd; k++) {
        float4 xa = *(const float4*)(xT + k * XT_STRIDE + r0);
        float4 xb = *(const float4*)(xT + k * XT_STRIDE + r0 + 4);
        float4 wa = *(const float4*)(wbase + k * Dd);
        float4 wb = *(const float4*)(wbase + k * Dd + 4);
        unsigned long long w0, w1, w2, w3;
        PACKAB(w0, wa.x, wa.y);
        PACKAB(w1, wa.z, wa.w);
        PACKAB(w2, wb.x, wb.y);
        PACKAB(w3, wb.z, wb.w);
        float xs[8] = {xa.x, xa.y, xa.z, xa.w, xb.x, xb.y, xb.z, xb.w};
#pragma unroll
        for (int r = 0; r < 8; r++) {
            unsigned long long x2;
            PACK2(x2, xs[r]);
            FMA2(acc[r][0], x2, w0);
            FMA2(acc[r][1], x2, w1);
            FMA2(acc[r][2], x2, w2);
            FMA2(acc[r][3], x2, w3);
        }
    }

    // epilogue: store h + alpha dot products (quad reduction across cg)
    float as8[8], ad8[8];
#pragma unroll
    for (int c = 0; c < 8; c++) {
        as8[c] = av[cg * 8 + c];
        ad8[c] = av[Dd + cg * 8 + c];
    }
    unsigned int qmask = 0xFu << ((tid & 31) & ~3);
#pragma unroll
    for (int r = 0; r < 8; r++) {
        int row = rowbase + r0 + r;
        unsigned int u[8];
        UNPACK2(u[0], u[1], acc[r][0]);
        UNPACK2(u[2], u[3], acc[r][1]);
        UNPACK2(u[4], u[5], acc[r][2]);
        UNPACK2(u[6], u[7], acc[r][3]);
        float c0 = __uint_as_float(u[0]), c1 = __uint_as_float(u[1]);
        float c2 = __uint_as_float(u[2]), c3 = __uint_as_float(u[3]);
        float c4 = __uint_as_float(u[4]), c5 = __uint_as_float(u[5]);
        float c6 = __uint_as_float(u[6]), c7 = __uint_as_float(u[7]);
        *(float4*)(g_h + row * Dd + cg * 8)     = make_float4(c0, c1, c2, c3);
        *(float4*)(g_h + row * Dd + cg * 8 + 4) = make_float4(c4, c5, c6, c7);
        float vs = c0 * as8[0] + c1 * as8[1] + c2 * as8[2] + c3 * as8[3]
                 + c4 * as8[4] + c5 * as8[5] + c6 * as8[6] + c7 * as8[7];
        float vd = c0 * ad8[0] + c1 * ad8[1] + c2 * ad8[2] + c3 * ad8[3]
                 + c4 * ad8[4] + c5 * ad8[5] + c6 * ad8[6] + c7 * ad8[7];
        vs += __shfl_xor_sync(qmask, vs, 1);
        vs += __shfl_xor_sync(qmask, vs, 2);
        vd += __shfl_xor_sync(qmask, vd, 1);
        vd += __shfl_xor_sync(qmask, vd, 2);
        if (cg == 0) {
            g_as[row] = vs;
            g_ad[row] = vd;
        }
    }
}

// ---------------------------------------------------------------------------
// Fused per-node GAT aggregation: TWO nodes per warp (16 lanes each).
// Single-shot 32-edge prologue per node; deg > 32 via rare uniform tail.
// reset != 0 (layer 2): re-arm g_cur[node] = 0 for the next graph replay.
// Softmax max-subtraction omitted (shift-invariant; alpha is O(10) bounded).
// ---------------------------------------------------------------------------
__global__ void __launch_bounds__(256, 8) k_node(const float* __restrict__ bias,
                                                 float* __restrict__ out,
                                                 int reset) {
    int warpid = (blockIdx.x * blockDim.x + threadIdx.x) >> 5;
    int lane = threadIdx.x & 31;
    int n0 = warpid << 1;
    if (n0 >= Nn) return;                          // Nn even -> n0+1 valid
    int half = lane >> 4;
    int hl   = lane & 15;
    int node = n0 + half;
    int eq   = hl >> 3;                            // 0/1: edge within pair
    int cs   = (hl & 7) << 2;                      // column start (4 cols)

    int   deg = g_cur[node];
    float adv = g_ad[node];
    int  slab = node << 6;

    // ---- prologue: 32 edge slots, two independent chains ----
    int s_lo = g_sorted[slab + hl];
    int s_hi = g_sorted[slab + 16 + hl];
    float as_lo = g_as[s_lo];                      // slots always readable
    float as_hi = g_as[s_hi];

    // self loop (independent chain too)
    float a0 = g_as[node] + adv;
    float w0 = __expf(leaky02(a0));
    const float4 hs = *(const float4*)(g_h + node * Dd + cs);

    if (reset && hl == 0) g_cur[node] = 0;         // re-arm for next replay

    float w_lo = (hl      < deg) ? __expf(leaky02(as_lo + adv)) : 0.f;
    float w_hi = (hl + 16 < deg) ? __expf(leaky02(as_hi + adv)) : 0.f;
    float wsum = w_lo + w_hi;

    int dmax = max(deg, __shfl_xor_sync(0xffffffffu, deg, 16));

    unsigned long long pacc0 = 0ull, pacc1 = 0ull; // packed float2 accums
    int sbase = (half << 4) + eq;                  // shfl source base

    // ---- FMA over lo edges (0..15) ----
#pragma unroll
    for (int j = 0; j < 16; j += 2) {
        if (j >= dmax) break;                      // uniform
        int   sj = __shfl_sync(0xffffffffu, s_lo, sbase + j);
        float wj = __shfl_sync(0xffffffffu, w_lo, sbase + j);
        ulonglong2 r = *(const ulonglong2*)(g_h + sj * Dd + cs);
        unsigned long long w2;
        PACK2(w2, wj);
        FMA2(pacc0, w2, r.x);
        FMA2(pacc1, w2, r.y);
    }
    // ---- FMA over hi edges (16..31) ----
#pragma unroll
    for (int j = 0; j < 16; j += 2) {
        if (j + 16 >= dmax) break;                 // uniform
        int   sj = __shfl_sync(0xffffffffu, s_hi, sbase + j);
        float wj = __shfl_sync(0xffffffffu, w_hi, sbase + j);
        ulonglong2 r = *(const ulonglong2*)(g_h + sj * Dd + cs);
        unsigned long long w2;
        PACK2(w2, wj);
        FMA2(pacc0, w2, r.x);
        FMA2(pacc1, w2, r.y);
    }

    // ---- rare tail: deg > 32 (uniform across warp) ----
    if (dmax > 32) {
        for (int k0 = 32; k0 < dmax; k0 += 16) {
            int idx = k0 + hl;
            int s = g_sorted[slab + (idx & 63)];
            float w = 0.f;
            if (idx < deg) w = __expf(leaky02(g_as[s] + adv));
            wsum += w;
            int nb = dmax - k0; if (nb > 16) nb = 16;
#pragma unroll
            for (int j = 0; j < 16; j += 2) {
                if (j >= nb) break;
                int   sj = __shfl_sync(0xffffffffu, s, sbase + j);
                float wj = __shfl_sync(0xffffffffu, w, sbase + j);
                ulonglong2 r = *(const ulonglong2*)(g_h + sj * Dd + cs);
                unsigned long long w2;
                PACK2(w2, wj);
                FMA2(pacc0, w2, r.x);
                FMA2(pacc1, w2, r.y);
            }
        }
    }

    unsigned int u0, u1, u2, u3;
    UNPACK2(u0, u1, pacc0);
    UNPACK2(u2, u3, pacc1);
    float acc0 = __uint_as_float(u0);
    float acc1 = __uint_as_float(u1);
    float acc2 = __uint_as_float(u2);
    float acc3 = __uint_as_float(u3);

    const float4 b4 = *(const float4*)(bias + cs); // hoisted: overlaps shfls

    // combine the 2 edge groups (offset 8, within each half)
    acc0 += __shfl_xor_sync(0xffffffffu, acc0, 8);
    acc1 += __shfl_xor_sync(0xffffffffu, acc1, 8);
    acc2 += __shfl_xor_sync(0xffffffffu, acc2, 8);
    acc3 += __shfl_xor_sync(0xffffffffu, acc3, 8);
    // wsum: reduce within the 16-lane half
#pragma unroll
    for (int o = 8; o > 0; o >>= 1)
        wsum += __shfl_xor_sync(0xffffffffu, wsum, o);

    // self loop contribution (once)
    acc0 = fmaf(w0, hs.x, acc0);
    acc1 = fmaf(w0, hs.y, acc1);
    acc2 = fmaf(w0, hs.z, acc2);
    acc3 = fmaf(w0, hs.w, acc3);
    wsum += w0;

    if (hl < 8) {                                  // 16 active lanes: 2 nodes
        float scale = __fdividef(1.f, wsum);
        float4 v;
        v.x = fmaf(acc0, scale, b4.x);
        v.y = fmaf(acc1, scale, b4.y);
        v.z = fmaf(acc2, scale, b4.z);
        v.w = fmaf(acc3, scale, b4.w);
        v.x = fast_elu(v.x);
        v.y = fast_elu(v.y);
        v.z = fast_elu(v.z);
        v.w = fast_elu(v.w);
        *(float4*)(out + node * Dd + cs) = v;
    }
}

// ---------------------------------------------------------------------------
extern "C" void kernel_launch(void* const* d_in, const int* in_sizes, int n_in,
                              void* d_out, int out_size) {
    const float* x    = (const float*)d_in[0];
    const int*   ei   = (const int*)d_in[1];
    const int4*  src4 = (const int4*)ei;
    const int4*  dst4 = (const int4*)(ei + Ee);
    const float* W1   = (const float*)d_in[2];
    const float* as1  = (const float*)d_in[3];
    const float* ad1  = (const float*)d_in[4];
    const float* b1   = (const float*)d_in[5];
    const float* W2   = (const float*)d_in[6];
    const float* as2  = (const float*)d_in[7];
    const float* ad2  = (const float*)d_in[8];
    const float* b2   = (const float*)d_in[9];

    float* xbar = (float*)d_out;            // first N*D: xbar
    float* z    = (float*)d_out + Nn * Dd;  // second N*D: z

    const int TPB = 256;
    const int E4  = Ee / 4;

    // ---- bucket build (shared by both layers); g_cur re-armed by layer 2 ----
    k_scatter<<<(E4 + TPB - 1) / TPB, TPB>>>(src4, dst4);

    const int gGemm = (Nn + 255) / 256;     // 256 rows per 128-thread block
    const int gNode = (Nn / 2 + 7) / 8;     // 8 warps/block, 2 nodes/warp

    // ---- Layer 1 ----
    k_gemm_alpha<<<gGemm, 128>>>(x, W1, as1, ad1);
    k_node      <<<gNode, TPB>>>(b1, z, 0);

    // ---- Layer 2 (resets g_cur for the next graph replay) ----
    k_gemm_alpha<<<gGemm, 128>>>(z, W2, as2, ad2);
    k_node      <<<gNode, TPB>>>(b2, xbar, 1);
}